// round 14
// baseline (speedup 1.0000x reference)
#include <cuda_runtime.h>
#include <math.h>

// ---- problem constants ----
#define NBATCH 4
#define NATOMS 600
#define NPAD   640
#define NBINS  64
#define BIN_W      0.1171875f            // 7.5/64 (exact fp32)
#define CUT_ADJ    7.734375f             // 7.5 + 2*BIN_W (exact)
#define GW         (7.5f / 63.0f)
#define GCOEFF     (-0.5f / (GW * GW))

// fine sub-histogram: 1024 bins, (count, moment) packed into one u64
#define NSUB       1024
#define SUBW       (CUT_ADJ / (float)NSUB)
#define INV_SUBW   ((float)NSUB / CUT_ADJ)
#define FIX        4194304.0f            // 2^22 fixed point for the moment
#define INV_FIX    (1.0f / 4194304.0f)
#define MBIAS      32768

// finalize window: 192 sub-bins (+-6.1 Gaussian widths), zero guards
#define PAD        96
#define SEG_LEN    12                    // 16 threads per final bin

// K1: 148 fat blocks (1/SM, one wave), 1024 threads
#define TPB        1024
#define WPB        32
#define BPB        37                    // blocks per batch
#define A_BLOCKS   (BPB * NBATCH)        // 148
#define IGRP       20                    // i-groups of 32
#define JLEN       10
#define NJC        60                    // j-chunks of 10
#define NTASK      600                   // upper-triangle tiles per batch

// static device scratch (zeroed at load; re-zeroed by K2 every call)
__device__ unsigned long long g_pk[NSUB];

// kept tiles per j-chunk (upper triangle): ig allowed in [0, KEPT(jc))
#define KEPT(q) ((10 * (q) + 8) / 32 + 1)

// =================== K1: pairs -> global packed sub-histogram ===================
__global__ void __launch_bounds__(TPB, 1)
rdf_pairs_kernel(const float* __restrict__ xyz) {
    __shared__ float4             s_pos[NPAD];          // 10.24 KB
    __shared__ unsigned long long s_pk[NSUB];           // 8 KB

    const int t    = threadIdx.x;
    const int lane = t & 31;
    const int w    = t >> 5;
    const int bat  = blockIdx.x / BPB;
    const int remb = blockIdx.x - bat * BPB;

    // stage this batch's positions (single round; NaN tail rejects pad atoms)
    const float* __restrict__ src = xyz + bat * NATOMS * 3;
    if (t < NPAD) {
        const float qnan = __int_as_float(0x7fffffff);
        float4 p;
        if (t < NATOMS) p = make_float4(src[3 * t], src[3 * t + 1], src[3 * t + 2], 0.0f);
        else            p = make_float4(qnan, qnan, qnan, 0.0f);
        s_pos[t] = p;
    }
    s_pk[t] = 0ull;
    __syncthreads();

    // balanced upper-triangle task assignment: tau = w*BPB + remb < NTASK
    const int tau = w * BPB + remb;
    if (tau < NTASK) {
        int jc = 0, base = 0;
        #pragma unroll
        for (int q = 0; q < NJC - 1; ++q) {
            const int k = KEPT(q);        // compile-time constant
            if (tau >= base + k) { base += k; jc = q + 1; }
        }
        const int ig = tau - base;

        const int i = ig * 32 + lane;
        const float4 pi = s_pos[i];
        const int j0 = jc * JLEN;
        const float cut2 = CUT_ADJ * CUT_ADJ;

        #pragma unroll
        for (int jj = 0; jj < JLEN; ++jj) {
            const int j = j0 + jj;
            float4 pj = s_pos[j];         // warp-uniform -> LDS broadcast
            float ax = fabsf(pj.x - pi.x);
            float ay = fabsf(pj.y - pi.y);
            float az = fabsf(pj.z - pi.z);
            float mx = fminf(ax, 20.0f - ax);
            float my = fminf(ay, 20.0f - ay);
            float mz = fminf(az, 20.0f - az);
            float ds = fmaf(mx, mx, fmaf(my, my, mz * mz));
            // unordered pairs (count scales by 1/2 exactly -> rdf invariant);
            // NaN pad atoms fail ds < cut2
            if (j > i && ds < cut2) {
                float d = ds * rsqrtf(ds);
                int s = (int)(d * INV_SUBW);
                if (s > NSUB - 1) s = NSUB - 1;
                float cs = ((float)s + 0.5f) * SUBW;
                int mq = __float2int_rn((d - cs) * FIX);
                unsigned long long pk =
                    (1ull << 32) | (unsigned long long)(unsigned)(mq + MBIAS);
                atomicAdd(&s_pk[s], pk);
            }
        }
    }
    __syncthreads();

    // flush: one sub-bin per thread, skip empties; kernel boundary = global sync
    unsigned long long pv = s_pk[t];
    if (pv) atomicAdd(&g_pk[t], pv);
}

// ============ K2: reconstruction + finalize (1 block, PDL-overlapped) ============
__global__ void __launch_bounds__(TPB, 1)
rdf_finalize_kernel(float* __restrict__ out, int out_size) {
    __shared__ float s_nf[NSUB + 2 * PAD];
    __shared__ float s_mf[NSUB + 2 * PAD];
    __shared__ float s_cnt[NBINS];
    __shared__ float s_part[2];
    __shared__ float s_total;

    const int t = threadIdx.x;

    // ---- pre-dependency work (overlaps K1 tail under PDL) ----
    // zero ONLY the guard regions; [PAD, PAD+NSUB) is fully overwritten below.
    if (t < PAD)            { s_nf[t] = 0.0f; s_mf[t] = 0.0f; }
    if (t >= TPB - PAD) {     // maps to indices PAD+NSUB .. NSUB+2*PAD-1
        const int k = t + 2 * PAD;
        s_nf[k] = 0.0f; s_mf[k] = 0.0f;
    }

    // wait for K1 grid completion (memory visible)
    cudaGridDependencySynchronize();

    {
        unsigned long long pv = g_pk[t];
        g_pk[t] = 0ull;                   // reset for next graph replay
        float n = (float)(unsigned)(pv >> 32);
        float m = ((float)(int)((unsigned)pv - (unsigned)(pv >> 32) * MBIAS)) * INV_FIX;
        s_nf[PAD + t] = n;
        s_mf[PAD + t] = m;
    }
    __syncthreads();

    // final bin k: 16 threads x 12 fixed-trip sub-bins; exp recurrence
    {
        const int k   = t >> 4;           // 0..63
        const int seg = t & 15;
        const float ck = (float)k * GW;
        const int s0 = __float2int_rn(ck * INV_SUBW) - 96 + seg * SEG_LEN;

        const float dlt = SUBW;
        float uu = ((float)s0 + 0.5f) * SUBW - ck;
        float e  = __expf(GCOEFF * uu * uu);
        float tt = __expf(GCOEFF * fmaf(2.0f * uu, dlt, dlt * dlt));
        const float q = __expf(2.0f * GCOEFF * dlt * dlt);

        float acc = 0.0f;
        #pragma unroll
        for (int ii = 0; ii < SEG_LEN; ++ii) {
            float n = s_nf[PAD + s0 + ii];
            float m = s_mf[PAD + s0 + ii];
            acc = fmaf(e, fmaf(2.0f * GCOEFF * uu, m, n), acc);  // n*f + m*f'
            e *= tt;
            tt *= q;
            uu += dlt;
        }
        acc += __shfl_xor_sync(0xffffffffu, acc, 1);
        acc += __shfl_xor_sync(0xffffffffu, acc, 2);
        acc += __shfl_xor_sync(0xffffffffu, acc, 4);
        acc += __shfl_xor_sync(0xffffffffu, acc, 8);
        if (seg == 0) s_cnt[k] = acc;
    }
    __syncthreads();

    // parallel total: 64 threads, shfl tree (replaces serial 64-LDS chain)
    if (t < 64) {
        float v = s_cnt[t];
        v += __shfl_xor_sync(0xffffffffu, v, 16);
        v += __shfl_xor_sync(0xffffffffu, v, 8);
        v += __shfl_xor_sync(0xffffffffu, v, 4);
        v += __shfl_xor_sync(0xffffffffu, v, 2);
        v += __shfl_xor_sync(0xffffffffu, v, 1);
        if ((t & 31) == 0) s_part[t >> 5] = v;
    }
    __syncthreads();
    if (t == 0) s_total = s_part[0] + s_part[1];
    __syncthreads();

    const float pi43 = 4.0f * 3.14159265358979f / 3.0f;
    const float num  = (2.0f * CUT_ADJ) * (2.0f * CUT_ADJ) * (2.0f * CUT_ADJ);
    if (out_size >= 2 * NBINS + 1) {
        // layout: BINS[65] then rdf[64]
        if (t <= NBINS) out[t] = (float)t * BIN_W;
        if (t < NBINS) {
            float b0 = (float)t * BIN_W;
            float b1 = (float)(t + 1) * BIN_W;
            float vol = pi43 * (b1 * b1 * b1 - b0 * b0 * b0);
            out[NBINS + 1 + t] = (s_cnt[t] / s_total) * num / (2.0f * vol);
        }
    } else {
        if (t < NBINS && t < out_size) {
            float b0 = (float)t * BIN_W;
            float b1 = (float)(t + 1) * BIN_W;
            float vol = pi43 * (b1 * b1 * b1 - b0 * b0 * b0);
            out[t] = (s_cnt[t] / s_total) * num / (2.0f * vol);
        }
    }
}

extern "C" void kernel_launch(void* const* d_in, const int* in_sizes, int n_in,
                              void* d_out, int out_size) {
    const float* xyz = (const float*)d_in[0];
    float* out = (float*)d_out;

    rdf_pairs_kernel<<<A_BLOCKS, TPB>>>(xyz);

    // K2 with Programmatic Dependent Launch: its launch latency + guard-zero
    // prologue overlap K1's tail; cudaGridDependencySynchronize() gates the
    // g_pk reads on K1 completion.
    cudaLaunchConfig_t cfg = {};
    cfg.gridDim  = dim3(1, 1, 1);
    cfg.blockDim = dim3(TPB, 1, 1);
    cfg.dynamicSmemBytes = 0;
    cfg.stream = 0;
    cudaLaunchAttribute attrs[1];
    attrs[0].id = cudaLaunchAttributeProgrammaticStreamSerialization;
    attrs[0].val.programmaticStreamSerializationAllowed = 1;
    cfg.attrs = attrs;
    cfg.numAttrs = 1;
    cudaLaunchKernelEx(&cfg, rdf_finalize_kernel, out, out_size);
}